// round 11
// baseline (speedup 1.0000x reference)
#include <cuda_runtime.h>
#include <cuda_fp16.h>
#include <cstdint>
#include <cstddef>

#define N_TOK 16384
#define HID   1024
#define FFN   2048
#define NEXP  8

static constexpr size_t XG_ELEMS   = (size_t)NEXP * N_TOK * HID;
static constexpr size_t HACT_ELEMS = (size_t)NEXP * N_TOK * FFN;
static constexpr size_t GW_ELEMS   = (size_t)NEXP * FFN * HID;

__device__ __align__(1024) __half g_Xg[XG_ELEMS];
__device__ __align__(1024) __half g_Hact[HACT_ELEMS];
__device__ __align__(1024) __half g_gwc[GW_ELEMS];
__device__ __align__(1024) __half g_uwc[GW_ELEMS];
__device__ __align__(1024) __half g_dwc[GW_ELEMS];
__device__ int   g_cnt[NEXP];
__device__ int   g_tok[NEXP * N_TOK];
__device__ float g_tw [NEXP * N_TOK];

// ============================ helpers ============================

__device__ __forceinline__ uint32_t smem_u32(const void* p) {
    uint32_t a;
    asm("{ .reg .u64 t; cvta.to.shared.u64 t, %1; cvt.u32.u64 %0, t; }"
        : "=r"(a) : "l"(p));
    return a;
}

#define CP_ASYNC_CG16(sa, gp) \
    asm volatile("cp.async.cg.shared.global [%0], [%1], 16;" :: "r"(sa), "l"(gp))
#define CP_COMMIT() asm volatile("cp.async.commit_group;" ::: "memory")
#define CP_WAIT_N(n) asm volatile("cp.async.wait_group %0;" :: "n"(n) : "memory")

// m16n8k16 f16 mma, f32 accumulate; C += A*B
__device__ __forceinline__ void mma16(float c[4], uint32_t a0, uint32_t a1,
                                      uint32_t a2, uint32_t a3,
                                      uint32_t b0, uint32_t b1) {
    asm volatile(
        "mma.sync.aligned.m16n8k16.row.col.f32.f16.f16.f32 "
        "{%0,%1,%2,%3}, {%4,%5,%6,%7}, {%8,%9}, {%0,%1,%2,%3};"
        : "+f"(c[0]), "+f"(c[1]), "+f"(c[2]), "+f"(c[3])
        : "r"(a0), "r"(a1), "r"(a2), "r"(a3), "r"(b0), "r"(b1));
}

// ldmatrix x4: 4 8x8 b16 matrices.
__device__ __forceinline__ void ldsm_x4(uint32_t& r0, uint32_t& r1,
                                        uint32_t& r2, uint32_t& r3, uint32_t addr) {
    asm volatile("ldmatrix.sync.aligned.m8n8.x4.shared.b16 {%0,%1,%2,%3}, [%4];"
                 : "=r"(r0), "=r"(r1), "=r"(r2), "=r"(r3) : "r"(addr));
}

// SMEM tile: rows x 64 halves (128 B data), row stride 144 B.
// Row-to-row bank step = 4 -> every ldmatrix 8-row phase covers all 32 banks
// exactly once (conflict-free); 144 is 16B-aligned for cp.async.
#define ROWB 144
#define TILEH64  (64  * ROWB)   // 9216
#define TILEH128 (128 * ROWB)   // 18432

// ROWS rows x 64 halves, NT threads. ldk/k0 in halves.
template <int ROWS, int NT>
__device__ __forceinline__ void load_tileH(const __half* __restrict__ g, int ldk,
                                           int k0, uint32_t sbase, int tid) {
#pragma unroll
    for (int j = 0; j < ROWS * 8 / NT; ++j) {
        int idx = j * NT + tid;
        int row = idx >> 3;
        int c16 = idx & 7;
        const __half* gp = g + (size_t)row * ldk + k0 + c16 * 8;
        uint32_t sa = sbase + (uint32_t)(row * ROWB + c16 * 16);
        CP_ASYNC_CG16(sa, gp);
    }
}

__device__ __forceinline__ float silu_mul(float gv, float uv) {
    float s = 1.0f / (1.0f + __expf(-gv));
    return gv * s * uv;
}

// ============================ small kernels ============================

__global__ void cvt_kernel(const float* __restrict__ s, __half* __restrict__ d, int n4) {
    int i = blockIdx.x * blockDim.x + threadIdx.x;
    if (i < n4) {
        float4 v = ((const float4*)s)[i];
        __half2 h0 = __floats2half2_rn(v.x, v.y);
        __half2 h1 = __floats2half2_rn(v.z, v.w);
        uint2 pk;
        pk.x = *reinterpret_cast<uint32_t*>(&h0);
        pk.y = *reinterpret_cast<uint32_t*>(&h1);
        ((uint2*)d)[i] = pk;
    }
}

// Fused router + gather: one block per token.
__global__ void __launch_bounds__(128) routergather_kernel(const float* __restrict__ X,
                                                           const float* __restrict__ Rw) {
    __shared__ float slog[NEXP];
    __shared__ int sd0, sd1;

    int n = blockIdx.x;
    int tid = threadIdx.x, warp = tid >> 5, lane = tid & 31;
    const float4* x4  = (const float4*)(X + (size_t)n * HID);
    const float4* rw4 = (const float4*)Rw;

    float a0 = 0.0f, a1 = 0.0f;
    int e0i = 2 * warp, e1i = 2 * warp + 1;
#pragma unroll
    for (int j = 0; j < 8; ++j) {
        int i = j * 32 + lane;
        float4 xv = x4[i];
        float4 r0 = rw4[e0i * (HID / 4) + i];
        float4 r1 = rw4[e1i * (HID / 4) + i];
        a0 += xv.x * r0.x + xv.y * r0.y + xv.z * r0.z + xv.w * r0.w;
        a1 += xv.x * r1.x + xv.y * r1.y + xv.z * r1.z + xv.w * r1.w;
    }
#pragma unroll
    for (int o = 16; o; o >>= 1) {
        a0 += __shfl_xor_sync(0xFFFFFFFFu, a0, o);
        a1 += __shfl_xor_sync(0xFFFFFFFFu, a1, o);
    }
    if (lane == 0) { slog[e0i] = a0; slog[e1i] = a1; }
    __syncthreads();

    if (tid == 0) {
        int e0 = 0;
#pragma unroll
        for (int e = 1; e < NEXP; ++e) if (slog[e] > slog[e0]) e0 = e;
        int e1 = (e0 == 0) ? 1 : 0;
#pragma unroll
        for (int e = 0; e < NEXP; ++e) if (e != e0 && slog[e] > slog[e1]) e1 = e;

        float w0 = 1.0f / (1.0f + expf(slog[e1] - slog[e0]));
        float w1 = 1.0f - w0;

        int s0 = atomicAdd(&g_cnt[e0], 1);
        int s1 = atomicAdd(&g_cnt[e1], 1);
        g_tok[e0 * N_TOK + s0] = n;  g_tw[e0 * N_TOK + s0] = w0;
        g_tok[e1 * N_TOK + s1] = n;  g_tw[e1 * N_TOK + s1] = w1;
        sd0 = e0 * N_TOK + s0;
        sd1 = e1 * N_TOK + s1;
    }
    __syncthreads();

    int d0 = sd0, d1 = sd1;
    uint2* o0 = (uint2*)(g_Xg + (size_t)d0 * HID);
    uint2* o1 = (uint2*)(g_Xg + (size_t)d1 * HID);
#pragma unroll
    for (int j = 0; j < 2; ++j) {
        int i = j * 128 + tid;
        float4 v = x4[i];
        __half2 h0 = __floats2half2_rn(v.x, v.y);
        __half2 h1 = __floats2half2_rn(v.z, v.w);
        uint2 pk;
        pk.x = *reinterpret_cast<uint32_t*>(&h0);
        pk.y = *reinterpret_cast<uint32_t*>(&h1);
        o0[i] = pk;
        o1[i] = pk;
    }
}

// ============================ GEMM 1: gate+up+SwiGLU ============================
// CTA tile 128x64 (g and u), 4 warps in 2x2 grid, warp tile 64x32 for both.
// 128-thread CTAs, occupancy 2. ldmatrix.x4; K-chunks of 64, S=3, 1 sync/chunk.

__global__ void __launch_bounds__(128, 2) gemm1_kernel() {
    constexpr int S = 3;
    constexpr int C = HID / 64;                            // 16 chunks
    constexpr int STAGE = TILEH128 + 2 * TILEH64;          // 36864

    extern __shared__ __align__(128) char smem[];
    uint32_t sb = smem_u32(smem);
    int tid = threadIdx.x;

    int e = blockIdx.z;
    int cnt = g_cnt[e];
    int m0 = blockIdx.y * 128;
    if (m0 >= cnt) return;
    int n0 = blockIdx.x * 64;

    const __half* A  = g_Xg  + ((size_t)e * N_TOK + m0) * HID;
    const __half* Bg = g_gwc + ((size_t)e * FFN + n0) * HID;
    const __half* Bu = g_uwc + ((size_t)e * FFN + n0) * HID;

    int warp = tid >> 5, lane = tid & 31;
    int wm = (warp >> 1) * 64;     // 0,64
    int wn = (warp & 1) * 32;      // 0,32
    int lg = lane >> 2;
    int lc = lane & 3;
    int gq = lane >> 3, rq = lane & 7;

    uint32_t aoff = (uint32_t)((wm + (gq & 1) * 8 + rq) * ROWB + (gq >> 1) * 16);
    uint32_t boff = (uint32_t)((wn + (gq >> 1) * 8 + rq) * ROWB + (gq & 1) * 16);

    float cg[4][4][4], cu[4][4][4];
#pragma unroll
    for (int mi = 0; mi < 4; ++mi)
#pragma unroll
        for (int ni = 0; ni < 4; ++ni)
#pragma unroll
            for (int r = 0; r < 4; ++r) { cg[mi][ni][r] = 0.0f; cu[mi][ni][r] = 0.0f; }

#pragma unroll
    for (int c = 0; c < S - 1; ++c) {
        uint32_t stb = sb + c * STAGE;
        load_tileH<128, 128>(A,  HID, c * 64, stb,               tid);
        load_tileH<64, 128>(Bg,  HID, c * 64, stb + TILEH128,    tid);
        load_tileH<64, 128>(Bu,  HID, c * 64, stb + TILEH128 + TILEH64, tid);
        CP_COMMIT();
    }

    for (int k = 0; k < C; ++k) {
        CP_WAIT_N(S - 2);
        __syncthreads();

        int cl = k + S - 1;
        if (cl < C) {
            uint32_t stb = sb + (cl % S) * STAGE;
            load_tileH<128, 128>(A,  HID, cl * 64, stb,               tid);
            load_tileH<64, 128>(Bg,  HID, cl * 64, stb + TILEH128,    tid);
            load_tileH<64, 128>(Bu,  HID, cl * 64, stb + TILEH128 + TILEH64, tid);
        }
        CP_COMMIT();

        uint32_t sA  = sb + (uint32_t)((k % S) * STAGE);
        uint32_t sBg = sA + TILEH128;
        uint32_t sBu = sBg + TILEH64;

#pragma unroll
        for (int t = 0; t < 4; ++t) {          // 4 x k16 per chunk
            uint32_t kb = (uint32_t)(t * 32);
            uint32_t a[4][4];
#pragma unroll
            for (int mi = 0; mi < 4; ++mi)
                ldsm_x4(a[mi][0], a[mi][1], a[mi][2], a[mi][3],
                        sA + aoff + (uint32_t)(mi * 16 * ROWB) + kb);

            uint32_t bg[4][2], bu[4][2];
            ldsm_x4(bg[0][0], bg[0][1], bg[1][0], bg[1][1], sBg + boff + kb);
            ldsm_x4(bg[2][0], bg[2][1], bg[3][0], bg[3][1], sBg + boff + 16 * ROWB + kb);
            ldsm_x4(bu[0][0], bu[0][1], bu[1][0], bu[1][1], sBu + boff + kb);
            ldsm_x4(bu[2][0], bu[2][1], bu[3][0], bu[3][1], sBu + boff + 16 * ROWB + kb);

#pragma unroll
            for (int mi = 0; mi < 4; ++mi)
#pragma unroll
                for (int ni = 0; ni < 4; ++ni) {
                    mma16(cg[mi][ni], a[mi][0], a[mi][1], a[mi][2], a[mi][3],
                          bg[ni][0], bg[ni][1]);
                    mma16(cu[mi][ni], a[mi][0], a[mi][1], a[mi][2], a[mi][3],
                          bu[ni][0], bu[ni][1]);
                }
        }
    }

#pragma unroll
    for (int mi = 0; mi < 4; ++mi) {
        int r0 = m0 + wm + mi * 16 + lg;
        int r1 = r0 + 8;
        bool v0 = r0 < cnt, v1 = r1 < cnt;
        __half* d0 = g_Hact + ((size_t)e * N_TOK + r0) * FFN + n0;
        __half* d1 = g_Hact + ((size_t)e * N_TOK + r1) * FFN + n0;
#pragma unroll
        for (int ni = 0; ni < 4; ++ni) {
            int col = wn + ni * 8 + lc * 2;
            if (v0) {
                __half2 h = __floats2half2_rn(silu_mul(cg[mi][ni][0], cu[mi][ni][0]),
                                              silu_mul(cg[mi][ni][1], cu[mi][ni][1]));
                *(__half2*)(d0 + col) = h;
            }
            if (v1) {
                __half2 h = __floats2half2_rn(silu_mul(cg[mi][ni][2], cu[mi][ni][2]),
                                              silu_mul(cg[mi][ni][3], cu[mi][ni][3]));
                *(__half2*)(d1 + col) = h;
            }
        }
    }
}

// ============================ GEMM 2: down + weighted scatter ============================
// CTA tile 128x128, 4 warps in 2x2 grid, warp tile 64x64 (mi=4, ni=8).
// 128-thread CTAs, occupancy 2. K-chunks of 64, S=3, 1 sync/chunk.

__global__ void __launch_bounds__(128, 2) gemm2_kernel(float* __restrict__ out) {
    constexpr int S = 3;
    constexpr int C = FFN / 64;                  // 32 chunks
    constexpr int STAGE = 2 * TILEH128;          // 36864

    extern __shared__ __align__(128) char smem[];
    uint32_t sb = smem_u32(smem);
    int tid = threadIdx.x;

    int e = blockIdx.z;
    int cnt = g_cnt[e];
    int m0 = blockIdx.y * 128;
    if (m0 >= cnt) return;
    int n0 = blockIdx.x * 128;

    const __half* A = g_Hact + ((size_t)e * N_TOK + m0) * FFN;
    const __half* B = g_dwc  + ((size_t)e * HID + n0) * FFN;

    int warp = tid >> 5, lane = tid & 31;
    int wm = (warp >> 1) * 64;     // 0,64
    int wn = (warp & 1) * 64;      // 0,64
    int lg = lane >> 2;
    int lc = lane & 3;
    int gq = lane >> 3, rq = lane & 7;

    uint32_t aoff = (uint32_t)((wm + (gq & 1) * 8 + rq) * ROWB + (gq >> 1) * 16);
    uint32_t boff = (uint32_t)((wn + (gq >> 1) * 8 + rq) * ROWB + (gq & 1) * 16);

    float cc[4][8][4];
#pragma unroll
    for (int mi = 0; mi < 4; ++mi)
#pragma unroll
        for (int ni = 0; ni < 8; ++ni)
#pragma unroll
            for (int r = 0; r < 4; ++r) cc[mi][ni][r] = 0.0f;

#pragma unroll
    for (int c = 0; c < S - 1; ++c) {
        uint32_t stb = sb + c * STAGE;
        load_tileH<128, 128>(A, FFN, c * 64, stb,            tid);
        load_tileH<128, 128>(B, FFN, c * 64, stb + TILEH128, tid);
        CP_COMMIT();
    }

    for (int k = 0; k < C; ++k) {
        CP_WAIT_N(S - 2);
        __syncthreads();

        int cl = k + S - 1;
        if (cl < C) {
            uint32_t stb = sb + (cl % S) * STAGE;
            load_tileH<128, 128>(A, FFN, cl * 64, stb,            tid);
            load_tileH<128, 128>(B, FFN, cl * 64, stb + TILEH128, tid);
        }
        CP_COMMIT();

        uint32_t sA = sb + (uint32_t)((k % S) * STAGE);
        uint32_t sB = sA + TILEH128;

#pragma unroll
        for (int t = 0; t < 4; ++t) {
            uint32_t kb = (uint32_t)(t * 32);
            uint32_t a[4][4];
#pragma unroll
            for (int mi = 0; mi < 4; ++mi)
                ldsm_x4(a[mi][0], a[mi][1], a[mi][2], a[mi][3],
                        sA + aoff + (uint32_t)(mi * 16 * ROWB) + kb);

            uint32_t b[8][2];
#pragma unroll
            for (int p = 0; p < 4; ++p)
                ldsm_x4(b[2 * p][0], b[2 * p][1], b[2 * p + 1][0], b[2 * p + 1][1],
                        sB + boff + (uint32_t)(p * 16 * ROWB) + kb);

#pragma unroll
            for (int mi = 0; mi < 4; ++mi)
#pragma unroll
                for (int ni = 0; ni < 8; ++ni)
                    mma16(cc[mi][ni], a[mi][0], a[mi][1], a[mi][2], a[mi][3],
                          b[ni][0], b[ni][1]);
        }
    }

    // epilogue: weighted atomic scatter to out[token]
#pragma unroll
    for (int mi = 0; mi < 4; ++mi) {
        int r0 = m0 + wm + mi * 16 + lg;
        int r1 = r0 + 8;
        bool v0 = r0 < cnt, v1 = r1 < cnt;
        int   t0 = v0 ? g_tok[e * N_TOK + r0] : 0;
        float w0 = v0 ? g_tw [e * N_TOK + r0] : 0.0f;
        int   t1 = v1 ? g_tok[e * N_TOK + r1] : 0;
        float w1 = v1 ? g_tw [e * N_TOK + r1] : 0.0f;
        float* o0 = out + (size_t)t0 * HID + n0;
        float* o1 = out + (size_t)t1 * HID + n0;
#pragma unroll
        for (int ni = 0; ni < 8; ++ni) {
            int col = wn + ni * 8 + lc * 2;
            if (v0) {
                atomicAdd(o0 + col,     w0 * cc[mi][ni][0]);
                atomicAdd(o0 + col + 1, w0 * cc[mi][ni][1]);
            }
            if (v1) {
                atomicAdd(o1 + col,     w1 * cc[mi][ni][2]);
                atomicAdd(o1 + col + 1, w1 * cc[mi][ni][3]);
            }
        }
    }
}

// ============================ host launcher ============================

extern "C" void kernel_launch(void* const* d_in, const int* in_sizes, int n_in,
                              void* d_out, int out_size) {
    (void)in_sizes; (void)n_in; (void)out_size;
    const float* X  = (const float*)d_in[0];
    const float* Rw = (const float*)d_in[1];
    const float* Gw = (const float*)d_in[2];
    const float* Uw = (const float*)d_in[3];
    const float* Dw = (const float*)d_in[4];
    float* out = (float*)d_out;

    void *pcnt, *pgw, *puw, *pdw;
    cudaGetSymbolAddress(&pcnt, g_cnt);
    cudaGetSymbolAddress(&pgw, g_gwc);
    cudaGetSymbolAddress(&puw, g_uwc);
    cudaGetSymbolAddress(&pdw, g_dwc);

    const int n4 = (int)(GW_ELEMS / 4);
    const int cb = 256;
    const int cg = (n4 + cb - 1) / cb;

    const int SMEM1 = 3 * (TILEH128 + 2 * TILEH64);   // 110592
    const int SMEM2 = 3 * (2 * TILEH128);             // 110592
    cudaFuncSetAttribute(gemm1_kernel, cudaFuncAttributeMaxDynamicSharedMemorySize, SMEM1);
    cudaFuncSetAttribute(gemm2_kernel, cudaFuncAttributeMaxDynamicSharedMemorySize, SMEM2);

    // ncu (-s 5 -c 1) profiles the 5th launch (1-based, memsets counted):
    // 1: memset(cnt)  2: routergather  3: cvtG  4: cvtU  5: gemm1
    // 6: cvtD  7: memset(out)  8: gemm2
    cudaMemsetAsync(pcnt, 0, NEXP * sizeof(int));
    routergather_kernel<<<N_TOK, 128>>>(X, Rw);
    cvt_kernel<<<cg, cb>>>(Gw, (__half*)pgw, n4);
    cvt_kernel<<<cg, cb>>>(Uw, (__half*)puw, n4);

    gemm1_kernel<<<dim3(FFN / 64, N_TOK / 128, NEXP), 128, SMEM1>>>();

    cvt_kernel<<<cg, cb>>>(Dw, (__half*)pdw, n4);
    cudaMemsetAsync(d_out, 0, (size_t)N_TOK * HID * sizeof(float));

    gemm2_kernel<<<dim3(HID / 128, N_TOK / 128, NEXP), 128, SMEM2>>>(out);
}

// round 12
// speedup vs baseline: 1.0529x; 1.0529x over previous
#include <cuda_runtime.h>
#include <cuda_fp16.h>
#include <cstdint>
#include <cstddef>

#define N_TOK 16384
#define HID   1024
#define FFN   2048
#define NEXP  8

static constexpr size_t XG_ELEMS   = (size_t)NEXP * N_TOK * HID;
static constexpr size_t HACT_ELEMS = (size_t)NEXP * N_TOK * FFN;
static constexpr size_t GW_ELEMS   = (size_t)NEXP * FFN * HID;
static constexpr size_t Y_ELEMS    = (size_t)NEXP * N_TOK * HID;

__device__ __align__(1024) __half g_Xg[XG_ELEMS];
__device__ __align__(1024) __half g_Hact[HACT_ELEMS];
__device__ __align__(1024) __half g_gwc[GW_ELEMS];
__device__ __align__(1024) __half g_uwc[GW_ELEMS];
__device__ __align__(1024) __half g_dwc[GW_ELEMS];
__device__ __align__(1024) float  g_Y[Y_ELEMS];
__device__ int   g_cnt[NEXP];
__device__ float g_tw [NEXP * N_TOK];
__device__ int   g_dst[2 * N_TOK];

// ============================ helpers ============================

__device__ __forceinline__ uint32_t smem_u32(const void* p) {
    uint32_t a;
    asm("{ .reg .u64 t; cvta.to.shared.u64 t, %1; cvt.u32.u64 %0, t; }"
        : "=r"(a) : "l"(p));
    return a;
}

#define CP_ASYNC_CG16(sa, gp) \
    asm volatile("cp.async.cg.shared.global [%0], [%1], 16;" :: "r"(sa), "l"(gp))
#define CP_COMMIT() asm volatile("cp.async.commit_group;" ::: "memory")
#define CP_WAIT_N(n) asm volatile("cp.async.wait_group %0;" :: "n"(n) : "memory")

// m16n8k16 f16 mma, f32 accumulate; C += A*B
__device__ __forceinline__ void mma16(float c[4], uint32_t a0, uint32_t a1,
                                      uint32_t a2, uint32_t a3,
                                      uint32_t b0, uint32_t b1) {
    asm volatile(
        "mma.sync.aligned.m16n8k16.row.col.f32.f16.f16.f32 "
        "{%0,%1,%2,%3}, {%4,%5,%6,%7}, {%8,%9}, {%0,%1,%2,%3};"
        : "+f"(c[0]), "+f"(c[1]), "+f"(c[2]), "+f"(c[3])
        : "r"(a0), "r"(a1), "r"(a2), "r"(a3), "r"(b0), "r"(b1));
}

// ldmatrix x4: 4 8x8 b16 matrices.
__device__ __forceinline__ void ldsm_x4(uint32_t& r0, uint32_t& r1,
                                        uint32_t& r2, uint32_t& r3, uint32_t addr) {
    asm volatile("ldmatrix.sync.aligned.m8n8.x4.shared.b16 {%0,%1,%2,%3}, [%4];"
                 : "=r"(r0), "=r"(r1), "=r"(r2), "=r"(r3) : "r"(addr));
}

// SMEM tile: rows x 64 halves (128 B data), row stride 144 B.
// Row-to-row bank step = 4 -> every ldmatrix 8-row phase covers all 32 banks
// exactly once (conflict-free); 144 is 16B-aligned for cp.async.
#define ROWB 144
#define TILEH64  (64  * ROWB)   // 9216
#define TILEH128 (128 * ROWB)   // 18432

// ROWS rows x 64 halves, 256 threads. ldk/k0 in halves.
template <int ROWS>
__device__ __forceinline__ void load_tileH(const __half* __restrict__ g, int ldk,
                                           int k0, uint32_t sbase, int tid) {
#pragma unroll
    for (int j = 0; j < ROWS / 32; ++j) {
        int idx = j * 256 + tid;
        int row = idx >> 3;
        int c16 = idx & 7;
        const __half* gp = g + (size_t)row * ldk + k0 + c16 * 8;
        uint32_t sa = sbase + (uint32_t)(row * ROWB + c16 * 16);
        CP_ASYNC_CG16(sa, gp);
    }
}

__device__ __forceinline__ float silu_mul(float gv, float uv) {
    float s = 1.0f / (1.0f + __expf(-gv));
    return gv * s * uv;
}

// ============================ small kernels ============================

// One kernel converts all three weight tensors (blockIdx.z selects).
__global__ void cvt3_kernel(const float* __restrict__ G, const float* __restrict__ U,
                            const float* __restrict__ D,
                            __half* __restrict__ dg, __half* __restrict__ du,
                            __half* __restrict__ dd, int n4) {
    int i = blockIdx.x * blockDim.x + threadIdx.x;
    if (i >= n4) return;
    const float* s = (blockIdx.z == 0) ? G : (blockIdx.z == 1) ? U : D;
    __half* d      = (blockIdx.z == 0) ? dg : (blockIdx.z == 1) ? du : dd;
    float4 v = ((const float4*)s)[i];
    __half2 h0 = __floats2half2_rn(v.x, v.y);
    __half2 h1 = __floats2half2_rn(v.z, v.w);
    uint2 pk;
    pk.x = *reinterpret_cast<uint32_t*>(&h0);
    pk.y = *reinterpret_cast<uint32_t*>(&h1);
    ((uint2*)d)[i] = pk;
}

// Fused router + gather: one block per token.
__global__ void __launch_bounds__(128) routergather_kernel(const float* __restrict__ X,
                                                           const float* __restrict__ Rw) {
    __shared__ float slog[NEXP];
    __shared__ int sd0, sd1;

    int n = blockIdx.x;
    int tid = threadIdx.x, warp = tid >> 5, lane = tid & 31;
    const float4* x4  = (const float4*)(X + (size_t)n * HID);
    const float4* rw4 = (const float4*)Rw;

    float a0 = 0.0f, a1 = 0.0f;
    int e0i = 2 * warp, e1i = 2 * warp + 1;
#pragma unroll
    for (int j = 0; j < 8; ++j) {
        int i = j * 32 + lane;
        float4 xv = x4[i];
        float4 r0 = rw4[e0i * (HID / 4) + i];
        float4 r1 = rw4[e1i * (HID / 4) + i];
        a0 += xv.x * r0.x + xv.y * r0.y + xv.z * r0.z + xv.w * r0.w;
        a1 += xv.x * r1.x + xv.y * r1.y + xv.z * r1.z + xv.w * r1.w;
    }
#pragma unroll
    for (int o = 16; o; o >>= 1) {
        a0 += __shfl_xor_sync(0xFFFFFFFFu, a0, o);
        a1 += __shfl_xor_sync(0xFFFFFFFFu, a1, o);
    }
    if (lane == 0) { slog[e0i] = a0; slog[e1i] = a1; }
    __syncthreads();

    if (tid == 0) {
        int e0 = 0;
#pragma unroll
        for (int e = 1; e < NEXP; ++e) if (slog[e] > slog[e0]) e0 = e;
        int e1 = (e0 == 0) ? 1 : 0;
#pragma unroll
        for (int e = 0; e < NEXP; ++e) if (e != e0 && slog[e] > slog[e1]) e1 = e;

        float w0 = 1.0f / (1.0f + expf(slog[e1] - slog[e0]));
        float w1 = 1.0f - w0;

        int s0 = atomicAdd(&g_cnt[e0], 1);
        int s1 = atomicAdd(&g_cnt[e1], 1);
        g_tw[e0 * N_TOK + s0] = w0;
        g_tw[e1 * N_TOK + s1] = w1;
        sd0 = e0 * N_TOK + s0;
        sd1 = e1 * N_TOK + s1;
        g_dst[2 * n]     = sd0;
        g_dst[2 * n + 1] = sd1;
    }
    __syncthreads();

    int d0 = sd0, d1 = sd1;
    uint2* o0 = (uint2*)(g_Xg + (size_t)d0 * HID);
    uint2* o1 = (uint2*)(g_Xg + (size_t)d1 * HID);
#pragma unroll
    for (int j = 0; j < 2; ++j) {
        int i = j * 128 + tid;
        float4 v = x4[i];
        __half2 h0 = __floats2half2_rn(v.x, v.y);
        __half2 h1 = __floats2half2_rn(v.z, v.w);
        uint2 pk;
        pk.x = *reinterpret_cast<uint32_t*>(&h0);
        pk.y = *reinterpret_cast<uint32_t*>(&h1);
        o0[i] = pk;
        o1[i] = pk;
    }
}

// Combine: out[n] = y[d0[n]] + y[d1[n]]  (weights already applied in gemm2).
__global__ void __launch_bounds__(128) combine_kernel(float* __restrict__ out) {
    int n = blockIdx.x;
    int d0 = g_dst[2 * n], d1 = g_dst[2 * n + 1];
    const float4* y0 = (const float4*)(g_Y + (size_t)d0 * HID);
    const float4* y1 = (const float4*)(g_Y + (size_t)d1 * HID);
    float4* o = (float4*)(out + (size_t)n * HID);
    int tid = threadIdx.x;
#pragma unroll
    for (int j = 0; j < 2; ++j) {
        int i = j * 128 + tid;
        float4 a = y0[i];
        float4 b = y1[i];
        a.x += b.x; a.y += b.y; a.z += b.z; a.w += b.w;
        o[i] = a;
    }
}

// ============================ GEMM 1: gate+up+SwiGLU ============================
// CTA tile 128x64 of BOTH gate and up. 8 warps in 4x2 grid, warp tile 32x32.
// ldmatrix.x4 fragment loads; K-chunks of 64, S=3 stages, 1 sync per chunk.

__global__ void __launch_bounds__(256, 2) gemm1_kernel() {
    constexpr int S = 3;
    constexpr int C = HID / 64;                            // 16 chunks
    constexpr int STAGE = TILEH128 + 2 * TILEH64;          // 36864

    extern __shared__ __align__(128) char smem[];
    uint32_t sb = smem_u32(smem);
    int tid = threadIdx.x;

    int e = blockIdx.z;
    int cnt = g_cnt[e];
    int m0 = blockIdx.y * 128;
    if (m0 >= cnt) return;
    int n0 = blockIdx.x * 64;

    const __half* A  = g_Xg  + ((size_t)e * N_TOK + m0) * HID;
    const __half* Bg = g_gwc + ((size_t)e * FFN + n0) * HID;
    const __half* Bu = g_uwc + ((size_t)e * FFN + n0) * HID;

    int warp = tid >> 5, lane = tid & 31;
    int wm = (warp >> 1) * 32;     // 0,32,64,96
    int wn = (warp & 1) * 32;      // 0,32
    int lg = lane >> 2;
    int lc = lane & 3;
    int gq = lane >> 3, rq = lane & 7;   // ldmatrix thread groups

    uint32_t aoff = (uint32_t)((wm + (gq & 1) * 8 + rq) * ROWB + (gq >> 1) * 16);
    uint32_t boff = (uint32_t)((wn + (gq >> 1) * 8 + rq) * ROWB + (gq & 1) * 16);

    float cg[2][4][4], cu[2][4][4];
#pragma unroll
    for (int mi = 0; mi < 2; ++mi)
#pragma unroll
        for (int ni = 0; ni < 4; ++ni)
#pragma unroll
            for (int r = 0; r < 4; ++r) { cg[mi][ni][r] = 0.0f; cu[mi][ni][r] = 0.0f; }

#pragma unroll
    for (int c = 0; c < S - 1; ++c) {
        uint32_t stb = sb + c * STAGE;
        load_tileH<128>(A,  HID, c * 64, stb,               tid);
        load_tileH<64>(Bg,  HID, c * 64, stb + TILEH128,    tid);
        load_tileH<64>(Bu,  HID, c * 64, stb + TILEH128 + TILEH64, tid);
        CP_COMMIT();
    }

    for (int k = 0; k < C; ++k) {
        CP_WAIT_N(S - 2);
        __syncthreads();

        int cl = k + S - 1;
        if (cl < C) {
            uint32_t stb = sb + (cl % S) * STAGE;
            load_tileH<128>(A,  HID, cl * 64, stb,               tid);
            load_tileH<64>(Bg,  HID, cl * 64, stb + TILEH128,    tid);
            load_tileH<64>(Bu,  HID, cl * 64, stb + TILEH128 + TILEH64, tid);
        }
        CP_COMMIT();

        uint32_t sA  = sb + (uint32_t)((k % S) * STAGE);
        uint32_t sBg = sA + TILEH128;
        uint32_t sBu = sBg + TILEH64;

#pragma unroll
        for (int t = 0; t < 4; ++t) {          // 4 x k16 per chunk
            uint32_t kb = (uint32_t)(t * 32);
            uint32_t a[2][4];
            ldsm_x4(a[0][0], a[0][1], a[0][2], a[0][3], sA + aoff + kb);
            ldsm_x4(a[1][0], a[1][1], a[1][2], a[1][3], sA + aoff + 16 * ROWB + kb);

            uint32_t bg[4][2], bu[4][2];
            ldsm_x4(bg[0][0], bg[0][1], bg[1][0], bg[1][1], sBg + boff + kb);
            ldsm_x4(bg[2][0], bg[2][1], bg[3][0], bg[3][1], sBg + boff + 16 * ROWB + kb);
            ldsm_x4(bu[0][0], bu[0][1], bu[1][0], bu[1][1], sBu + boff + kb);
            ldsm_x4(bu[2][0], bu[2][1], bu[3][0], bu[3][1], sBu + boff + 16 * ROWB + kb);

#pragma unroll
            for (int mi = 0; mi < 2; ++mi)
#pragma unroll
                for (int ni = 0; ni < 4; ++ni) {
                    mma16(cg[mi][ni], a[mi][0], a[mi][1], a[mi][2], a[mi][3],
                          bg[ni][0], bg[ni][1]);
                    mma16(cu[mi][ni], a[mi][0], a[mi][1], a[mi][2], a[mi][3],
                          bu[ni][0], bu[ni][1]);
                }
        }
    }

#pragma unroll
    for (int mi = 0; mi < 2; ++mi) {
        int r0 = m0 + wm + mi * 16 + lg;
        int r1 = r0 + 8;
        bool v0 = r0 < cnt, v1 = r1 < cnt;
        __half* d0 = g_Hact + ((size_t)e * N_TOK + r0) * FFN + n0;
        __half* d1 = g_Hact + ((size_t)e * N_TOK + r1) * FFN + n0;
#pragma unroll
        for (int ni = 0; ni < 4; ++ni) {
            int col = wn + ni * 8 + lc * 2;
            if (v0) {
                __half2 h = __floats2half2_rn(silu_mul(cg[mi][ni][0], cu[mi][ni][0]),
                                              silu_mul(cg[mi][ni][1], cu[mi][ni][1]));
                *(__half2*)(d0 + col) = h;
            }
            if (v1) {
                __half2 h = __floats2half2_rn(silu_mul(cg[mi][ni][2], cu[mi][ni][2]),
                                              silu_mul(cg[mi][ni][3], cu[mi][ni][3]));
                *(__half2*)(d1 + col) = h;
            }
        }
    }
}

// ============================ GEMM 2: down + weighted store ============================
// CTA tile 128x128, 8 warps in 4x2 grid, warp tile 32x64 (mi=2, ni=8).
// Epilogue: y[slot] = w * acc (plain STG, no atomics); combine kernel sums.

__global__ void __launch_bounds__(256, 2) gemm2_kernel() {
    constexpr int S = 3;
    constexpr int C = FFN / 64;                  // 32 chunks
    constexpr int STAGE = 2 * TILEH128;          // 36864

    extern __shared__ __align__(128) char smem[];
    uint32_t sb = smem_u32(smem);
    int tid = threadIdx.x;

    int e = blockIdx.z;
    int cnt = g_cnt[e];
    int m0 = blockIdx.y * 128;
    if (m0 >= cnt) return;
    int n0 = blockIdx.x * 128;

    const __half* A = g_Hact + ((size_t)e * N_TOK + m0) * FFN;
    const __half* B = g_dwc  + ((size_t)e * HID + n0) * FFN;

    int warp = tid >> 5, lane = tid & 31;
    int wm = (warp >> 1) * 32;     // 0,32,64,96
    int wn = (warp & 1) * 64;      // 0,64
    int lg = lane >> 2;
    int lc = lane & 3;
    int gq = lane >> 3, rq = lane & 7;

    uint32_t aoff = (uint32_t)((wm + (gq & 1) * 8 + rq) * ROWB + (gq >> 1) * 16);
    uint32_t boff = (uint32_t)((wn + (gq >> 1) * 8 + rq) * ROWB + (gq & 1) * 16);

    float cc[2][8][4];
#pragma unroll
    for (int mi = 0; mi < 2; ++mi)
#pragma unroll
        for (int ni = 0; ni < 8; ++ni)
#pragma unroll
            for (int r = 0; r < 4; ++r) cc[mi][ni][r] = 0.0f;

#pragma unroll
    for (int c = 0; c < S - 1; ++c) {
        uint32_t stb = sb + c * STAGE;
        load_tileH<128>(A, FFN, c * 64, stb,            tid);
        load_tileH<128>(B, FFN, c * 64, stb + TILEH128, tid);
        CP_COMMIT();
    }

    for (int k = 0; k < C; ++k) {
        CP_WAIT_N(S - 2);
        __syncthreads();

        int cl = k + S - 1;
        if (cl < C) {
            uint32_t stb = sb + (cl % S) * STAGE;
            load_tileH<128>(A, FFN, cl * 64, stb,            tid);
            load_tileH<128>(B, FFN, cl * 64, stb + TILEH128, tid);
        }
        CP_COMMIT();

        uint32_t sA = sb + (uint32_t)((k % S) * STAGE);
        uint32_t sB = sA + TILEH128;

#pragma unroll
        for (int t = 0; t < 4; ++t) {
            uint32_t kb = (uint32_t)(t * 32);
            uint32_t a[2][4];
            ldsm_x4(a[0][0], a[0][1], a[0][2], a[0][3], sA + aoff + kb);
            ldsm_x4(a[1][0], a[1][1], a[1][2], a[1][3], sA + aoff + 16 * ROWB + kb);

            uint32_t b[8][2];
#pragma unroll
            for (int p = 0; p < 4; ++p)
                ldsm_x4(b[2 * p][0], b[2 * p][1], b[2 * p + 1][0], b[2 * p + 1][1],
                        sB + boff + (uint32_t)(p * 16 * ROWB) + kb);

#pragma unroll
            for (int mi = 0; mi < 2; ++mi)
#pragma unroll
                for (int ni = 0; ni < 8; ++ni)
                    mma16(cc[mi][ni], a[mi][0], a[mi][1], a[mi][2], a[mi][3],
                          b[ni][0], b[ni][1]);
        }
    }

    // epilogue: weighted plain store into per-slot staging buffer
#pragma unroll
    for (int mi = 0; mi < 2; ++mi) {
        int r0 = m0 + wm + mi * 16 + lg;
        int r1 = r0 + 8;
        bool v0 = r0 < cnt, v1 = r1 < cnt;
        float w0 = v0 ? g_tw[e * N_TOK + r0] : 0.0f;
        float w1 = v1 ? g_tw[e * N_TOK + r1] : 0.0f;
        float* o0 = g_Y + ((size_t)e * N_TOK + r0) * HID + n0;
        float* o1 = g_Y + ((size_t)e * N_TOK + r1) * HID + n0;
#pragma unroll
        for (int ni = 0; ni < 8; ++ni) {
            int col = wn + ni * 8 + lc * 2;
            if (v0) {
                float2 p;
                p.x = w0 * cc[mi][ni][0];
                p.y = w0 * cc[mi][ni][1];
                *(float2*)(o0 + col) = p;
            }
            if (v1) {
                float2 p;
                p.x = w1 * cc[mi][ni][2];
                p.y = w1 * cc[mi][ni][3];
                *(float2*)(o1 + col) = p;
            }
        }
    }
}

// ============================ host launcher ============================

extern "C" void kernel_launch(void* const* d_in, const int* in_sizes, int n_in,
                              void* d_out, int out_size) {
    (void)in_sizes; (void)n_in; (void)out_size;
    const float* X  = (const float*)d_in[0];
    const float* Rw = (const float*)d_in[1];
    const float* Gw = (const float*)d_in[2];
    const float* Uw = (const float*)d_in[3];
    const float* Dw = (const float*)d_in[4];
    float* out = (float*)d_out;

    void *pcnt, *pgw, *puw, *pdw;
    cudaGetSymbolAddress(&pcnt, g_cnt);
    cudaGetSymbolAddress(&pgw, g_gwc);
    cudaGetSymbolAddress(&puw, g_uwc);
    cudaGetSymbolAddress(&pdw, g_dwc);

    const int n4 = (int)(GW_ELEMS / 4);
    const int cb = 256;
    const int cg = (n4 + cb - 1) / cb;

    const int SMEM1 = 3 * (TILEH128 + 2 * TILEH64);   // 110592
    const int SMEM2 = 3 * (2 * TILEH128);             // 110592
    cudaFuncSetAttribute(gemm1_kernel, cudaFuncAttributeMaxDynamicSharedMemorySize, SMEM1);
    cudaFuncSetAttribute(gemm2_kernel, cudaFuncAttributeMaxDynamicSharedMemorySize, SMEM2);

    // ncu (-s 5 -c 1) profiles the 5th launch (1-based, memsets counted):
    // 1: memset(cnt)  2: routergather  3: cvt3  4: gemm1  5: gemm2  6: combine
    cudaMemsetAsync(pcnt, 0, NEXP * sizeof(int));
    routergather_kernel<<<N_TOK, 128>>>(X, Rw);
    cvt3_kernel<<<dim3(cg, 1, 3), cb>>>(Gw, Uw, Dw,
                                        (__half*)pgw, (__half*)puw, (__half*)pdw, n4);

    gemm1_kernel<<<dim3(FFN / 64, N_TOK / 128, NEXP), 256, SMEM1>>>();
    gemm2_kernel<<<dim3(HID / 128, N_TOK / 128, NEXP), 256, SMEM2>>>();
    combine_kernel<<<N_TOK, 128>>>(out);
}

// round 13
// speedup vs baseline: 1.0955x; 1.0404x over previous
#include <cuda_runtime.h>
#include <cuda_fp16.h>
#include <cstdint>
#include <cstddef>

#define N_TOK 16384
#define HID   1024
#define FFN   2048
#define NEXP  8

static constexpr size_t XG_ELEMS   = (size_t)NEXP * N_TOK * HID;
static constexpr size_t HACT_ELEMS = (size_t)NEXP * N_TOK * FFN;
static constexpr size_t GW_ELEMS   = (size_t)NEXP * FFN * HID;
static constexpr size_t Y_ELEMS    = (size_t)NEXP * N_TOK * HID;

__device__ __align__(1024) __half g_Xg[XG_ELEMS];
__device__ __align__(1024) __half g_Hact[HACT_ELEMS];
__device__ __align__(1024) __half g_gwc[GW_ELEMS];
__device__ __align__(1024) __half g_uwc[GW_ELEMS];
__device__ __align__(1024) __half g_dwc[GW_ELEMS];
__device__ __align__(1024) float  g_Y[Y_ELEMS];
__device__ int   g_cnt[NEXP];
__device__ float g_tw [NEXP * N_TOK];
__device__ int   g_dst[2 * N_TOK];

// ============================ helpers ============================

__device__ __forceinline__ uint32_t smem_u32(const void* p) {
    uint32_t a;
    asm("{ .reg .u64 t; cvta.to.shared.u64 t, %1; cvt.u32.u64 %0, t; }"
        : "=r"(a) : "l"(p));
    return a;
}

#define CP_ASYNC_CG16(sa, gp) \
    asm volatile("cp.async.cg.shared.global [%0], [%1], 16;" :: "r"(sa), "l"(gp))
#define CP_COMMIT() asm volatile("cp.async.commit_group;" ::: "memory")
#define CP_WAIT_N(n) asm volatile("cp.async.wait_group %0;" :: "n"(n) : "memory")

// m16n8k16 f16 mma, f32 accumulate; C += A*B
__device__ __forceinline__ void mma16(float c[4], uint32_t a0, uint32_t a1,
                                      uint32_t a2, uint32_t a3,
                                      uint32_t b0, uint32_t b1) {
    asm volatile(
        "mma.sync.aligned.m16n8k16.row.col.f32.f16.f16.f32 "
        "{%0,%1,%2,%3}, {%4,%5,%6,%7}, {%8,%9}, {%0,%1,%2,%3};"
        : "+f"(c[0]), "+f"(c[1]), "+f"(c[2]), "+f"(c[3])
        : "r"(a0), "r"(a1), "r"(a2), "r"(a3), "r"(b0), "r"(b1));
}

// ldmatrix x4: 4 8x8 b16 matrices.
__device__ __forceinline__ void ldsm_x4(uint32_t& r0, uint32_t& r1,
                                        uint32_t& r2, uint32_t& r3, uint32_t addr) {
    asm volatile("ldmatrix.sync.aligned.m8n8.x4.shared.b16 {%0,%1,%2,%3}, [%4];"
                 : "=r"(r0), "=r"(r1), "=r"(r2), "=r"(r3) : "r"(addr));
}

// SMEM tile: rows x 64 halves (128 B data), row stride 144 B.
// Row-to-row bank step = 4 -> every ldmatrix 8-row phase covers all 32 banks
// exactly once (conflict-free); 144 is 16B-aligned for cp.async.
#define ROWB 144
#define TILEH64  (64  * ROWB)   // 9216
#define TILEH128 (128 * ROWB)   // 18432

// ROWS rows x 64 halves, NT threads. ldk/k0 in halves.
template <int ROWS, int NT>
__device__ __forceinline__ void load_tileH(const __half* __restrict__ g, int ldk,
                                           int k0, uint32_t sbase, int tid) {
#pragma unroll
    for (int j = 0; j < ROWS * 8 / NT; ++j) {
        int idx = j * NT + tid;
        int row = idx >> 3;
        int c16 = idx & 7;
        const __half* gp = g + (size_t)row * ldk + k0 + c16 * 8;
        uint32_t sa = sbase + (uint32_t)(row * ROWB + c16 * 16);
        CP_ASYNC_CG16(sa, gp);
    }
}

__device__ __forceinline__ float silu_mul(float gv, float uv) {
    float s = 1.0f / (1.0f + __expf(-gv));
    return gv * s * uv;
}

// ============================ small kernels ============================

// One kernel converts all three weight tensors (blockIdx.z selects).
__global__ void cvt3_kernel(const float* __restrict__ G, const float* __restrict__ U,
                            const float* __restrict__ D,
                            __half* __restrict__ dg, __half* __restrict__ du,
                            __half* __restrict__ dd, int n4) {
    int i = blockIdx.x * blockDim.x + threadIdx.x;
    if (i >= n4) return;
    const float* s = (blockIdx.z == 0) ? G : (blockIdx.z == 1) ? U : D;
    __half* d      = (blockIdx.z == 0) ? dg : (blockIdx.z == 1) ? du : dd;
    float4 v = ((const float4*)s)[i];
    __half2 h0 = __floats2half2_rn(v.x, v.y);
    __half2 h1 = __floats2half2_rn(v.z, v.w);
    uint2 pk;
    pk.x = *reinterpret_cast<uint32_t*>(&h0);
    pk.y = *reinterpret_cast<uint32_t*>(&h1);
    ((uint2*)d)[i] = pk;
}

// Fused router + gather: one block per token.
__global__ void __launch_bounds__(128) routergather_kernel(const float* __restrict__ X,
                                                           const float* __restrict__ Rw) {
    __shared__ float slog[NEXP];
    __shared__ int sd0, sd1;

    int n = blockIdx.x;
    int tid = threadIdx.x, warp = tid >> 5, lane = tid & 31;
    const float4* x4  = (const float4*)(X + (size_t)n * HID);
    const float4* rw4 = (const float4*)Rw;

    float a0 = 0.0f, a1 = 0.0f;
    int e0i = 2 * warp, e1i = 2 * warp + 1;
#pragma unroll
    for (int j = 0; j < 8; ++j) {
        int i = j * 32 + lane;
        float4 xv = x4[i];
        float4 r0 = rw4[e0i * (HID / 4) + i];
        float4 r1 = rw4[e1i * (HID / 4) + i];
        a0 += xv.x * r0.x + xv.y * r0.y + xv.z * r0.z + xv.w * r0.w;
        a1 += xv.x * r1.x + xv.y * r1.y + xv.z * r1.z + xv.w * r1.w;
    }
#pragma unroll
    for (int o = 16; o; o >>= 1) {
        a0 += __shfl_xor_sync(0xFFFFFFFFu, a0, o);
        a1 += __shfl_xor_sync(0xFFFFFFFFu, a1, o);
    }
    if (lane == 0) { slog[e0i] = a0; slog[e1i] = a1; }
    __syncthreads();

    if (tid == 0) {
        int e0 = 0;
#pragma unroll
        for (int e = 1; e < NEXP; ++e) if (slog[e] > slog[e0]) e0 = e;
        int e1 = (e0 == 0) ? 1 : 0;
#pragma unroll
        for (int e = 0; e < NEXP; ++e) if (e != e0 && slog[e] > slog[e1]) e1 = e;

        float w0 = 1.0f / (1.0f + expf(slog[e1] - slog[e0]));
        float w1 = 1.0f - w0;

        int s0 = atomicAdd(&g_cnt[e0], 1);
        int s1 = atomicAdd(&g_cnt[e1], 1);
        g_tw[e0 * N_TOK + s0] = w0;
        g_tw[e1 * N_TOK + s1] = w1;
        sd0 = e0 * N_TOK + s0;
        sd1 = e1 * N_TOK + s1;
        g_dst[2 * n]     = sd0;
        g_dst[2 * n + 1] = sd1;
    }
    __syncthreads();

    int d0 = sd0, d1 = sd1;
    uint2* o0 = (uint2*)(g_Xg + (size_t)d0 * HID);
    uint2* o1 = (uint2*)(g_Xg + (size_t)d1 * HID);
#pragma unroll
    for (int j = 0; j < 2; ++j) {
        int i = j * 128 + tid;
        float4 v = x4[i];
        __half2 h0 = __floats2half2_rn(v.x, v.y);
        __half2 h1 = __floats2half2_rn(v.z, v.w);
        uint2 pk;
        pk.x = *reinterpret_cast<uint32_t*>(&h0);
        pk.y = *reinterpret_cast<uint32_t*>(&h1);
        o0[i] = pk;
        o1[i] = pk;
    }
}

// Combine: out[n] = y[d0[n]] + y[d1[n]]  (weights already applied in gemm2).
__global__ void __launch_bounds__(128) combine_kernel(float* __restrict__ out) {
    int n = blockIdx.x;
    int d0 = g_dst[2 * n], d1 = g_dst[2 * n + 1];
    const float4* y0 = (const float4*)(g_Y + (size_t)d0 * HID);
    const float4* y1 = (const float4*)(g_Y + (size_t)d1 * HID);
    float4* o = (float4*)(out + (size_t)n * HID);
    int tid = threadIdx.x;
#pragma unroll
    for (int j = 0; j < 2; ++j) {
        int i = j * 128 + tid;
        float4 a = y0[i];
        float4 b = y1[i];
        a.x += b.x; a.y += b.y; a.z += b.z; a.w += b.w;
        o[i] = a;
    }
}

// ============================ GEMM 1: gate+up+SwiGLU ============================
// CTA tile 64x64 (g and u), 4 warps in 2x2 grid, warp tile 32x32 for both.
// S=2 double buffer, occupancy 4 (16 warps/SM in 4 barrier domains).

__global__ void __launch_bounds__(128, 4) gemm1_kernel() {
    constexpr int S = 2;
    constexpr int C = HID / 64;                 // 16 chunks
    constexpr int STAGE = 3 * TILEH64;          // A + Bg + Bu = 27648

    extern __shared__ __align__(128) char smem[];
    uint32_t sb = smem_u32(smem);
    int tid = threadIdx.x;

    int e = blockIdx.z;
    int cnt = g_cnt[e];
    int m0 = blockIdx.y * 64;
    if (m0 >= cnt) return;
    int n0 = blockIdx.x * 64;

    const __half* A  = g_Xg  + ((size_t)e * N_TOK + m0) * HID;
    const __half* Bg = g_gwc + ((size_t)e * FFN + n0) * HID;
    const __half* Bu = g_uwc + ((size_t)e * FFN + n0) * HID;

    int warp = tid >> 5, lane = tid & 31;
    int wm = (warp >> 1) * 32;     // 0,32
    int wn = (warp & 1) * 32;      // 0,32
    int lg = lane >> 2;
    int lc = lane & 3;
    int gq = lane >> 3, rq = lane & 7;   // ldmatrix thread groups

    uint32_t aoff = (uint32_t)((wm + (gq & 1) * 8 + rq) * ROWB + (gq >> 1) * 16);
    uint32_t boff = (uint32_t)((wn + (gq >> 1) * 8 + rq) * ROWB + (gq & 1) * 16);

    float cg[2][4][4], cu[2][4][4];
#pragma unroll
    for (int mi = 0; mi < 2; ++mi)
#pragma unroll
        for (int ni = 0; ni < 4; ++ni)
#pragma unroll
            for (int r = 0; r < 4; ++r) { cg[mi][ni][r] = 0.0f; cu[mi][ni][r] = 0.0f; }

    // prologue: chunk 0 into stage 0
    load_tileH<64, 128>(A,  HID, 0, sb,                tid);
    load_tileH<64, 128>(Bg, HID, 0, sb + TILEH64,      tid);
    load_tileH<64, 128>(Bu, HID, 0, sb + 2 * TILEH64,  tid);
    CP_COMMIT();

    for (int k = 0; k < C; ++k) {
        CP_WAIT_N(0);
        __syncthreads();

        int cl = k + 1;
        if (cl < C) {
            uint32_t stb = sb + (cl & 1) * STAGE;
            load_tileH<64, 128>(A,  HID, cl * 64, stb,               tid);
            load_tileH<64, 128>(Bg, HID, cl * 64, stb + TILEH64,     tid);
            load_tileH<64, 128>(Bu, HID, cl * 64, stb + 2 * TILEH64, tid);
            CP_COMMIT();
        }

        uint32_t sA  = sb + (uint32_t)((k & 1) * STAGE);
        uint32_t sBg = sA + TILEH64;
        uint32_t sBu = sBg + TILEH64;

#pragma unroll
        for (int t = 0; t < 4; ++t) {          // 4 x k16 per chunk
            uint32_t kb = (uint32_t)(t * 32);
            uint32_t a[2][4];
            ldsm_x4(a[0][0], a[0][1], a[0][2], a[0][3], sA + aoff + kb);
            ldsm_x4(a[1][0], a[1][1], a[1][2], a[1][3], sA + aoff + 16 * ROWB + kb);

            uint32_t bg[4][2], bu[4][2];
            ldsm_x4(bg[0][0], bg[0][1], bg[1][0], bg[1][1], sBg + boff + kb);
            ldsm_x4(bg[2][0], bg[2][1], bg[3][0], bg[3][1], sBg + boff + 16 * ROWB + kb);
            ldsm_x4(bu[0][0], bu[0][1], bu[1][0], bu[1][1], sBu + boff + kb);
            ldsm_x4(bu[2][0], bu[2][1], bu[3][0], bu[3][1], sBu + boff + 16 * ROWB + kb);

#pragma unroll
            for (int mi = 0; mi < 2; ++mi)
#pragma unroll
                for (int ni = 0; ni < 4; ++ni) {
                    mma16(cg[mi][ni], a[mi][0], a[mi][1], a[mi][2], a[mi][3],
                          bg[ni][0], bg[ni][1]);
                    mma16(cu[mi][ni], a[mi][0], a[mi][1], a[mi][2], a[mi][3],
                          bu[ni][0], bu[ni][1]);
                }
        }
    }

#pragma unroll
    for (int mi = 0; mi < 2; ++mi) {
        int r0 = m0 + wm + mi * 16 + lg;
        int r1 = r0 + 8;
        bool v0 = r0 < cnt, v1 = r1 < cnt;
        __half* d0 = g_Hact + ((size_t)e * N_TOK + r0) * FFN + n0;
        __half* d1 = g_Hact + ((size_t)e * N_TOK + r1) * FFN + n0;
#pragma unroll
        for (int ni = 0; ni < 4; ++ni) {
            int col = wn + ni * 8 + lc * 2;
            if (v0) {
                __half2 h = __floats2half2_rn(silu_mul(cg[mi][ni][0], cu[mi][ni][0]),
                                              silu_mul(cg[mi][ni][1], cu[mi][ni][1]));
                *(__half2*)(d0 + col) = h;
            }
            if (v1) {
                __half2 h = __floats2half2_rn(silu_mul(cg[mi][ni][2], cu[mi][ni][2]),
                                              silu_mul(cg[mi][ni][3], cu[mi][ni][3]));
                *(__half2*)(d1 + col) = h;
            }
        }
    }
}

// ============================ GEMM 2: down + weighted store ============================
// CTA tile 64x128, 4 warps in 2x2 grid, warp tile 32x64 (mi=2, ni=8).
// S=2 double buffer, occupancy 4. Plain weighted STG into g_Y; combine sums.

__global__ void __launch_bounds__(128, 4) gemm2_kernel() {
    constexpr int S = 2;
    constexpr int C = FFN / 64;                  // 32 chunks
    constexpr int STAGE = TILEH64 + TILEH128;    // 27648

    extern __shared__ __align__(128) char smem[];
    uint32_t sb = smem_u32(smem);
    int tid = threadIdx.x;

    int e = blockIdx.z;
    int cnt = g_cnt[e];
    int m0 = blockIdx.y * 64;
    if (m0 >= cnt) return;
    int n0 = blockIdx.x * 128;

    const __half* A = g_Hact + ((size_t)e * N_TOK + m0) * FFN;
    const __half* B = g_dwc  + ((size_t)e * HID + n0) * FFN;

    int warp = tid >> 5, lane = tid & 31;
    int wm = (warp >> 1) * 32;     // 0,32
    int wn = (warp & 1) * 64;      // 0,64
    int lg = lane >> 2;
    int lc = lane & 3;
    int gq = lane >> 3, rq = lane & 7;

    uint32_t aoff = (uint32_t)((wm + (gq & 1) * 8 + rq) * ROWB + (gq >> 1) * 16);
    uint32_t boff = (uint32_t)((wn + (gq >> 1) * 8 + rq) * ROWB + (gq & 1) * 16);

    float cc[2][8][4];
#pragma unroll
    for (int mi = 0; mi < 2; ++mi)
#pragma unroll
        for (int ni = 0; ni < 8; ++ni)
#pragma unroll
            for (int r = 0; r < 4; ++r) cc[mi][ni][r] = 0.0f;

    load_tileH<64, 128>(A, FFN, 0, sb,           tid);
    load_tileH<128, 128>(B, FFN, 0, sb + TILEH64, tid);
    CP_COMMIT();

    for (int k = 0; k < C; ++k) {
        CP_WAIT_N(0);
        __syncthreads();

        int cl = k + 1;
        if (cl < C) {
            uint32_t stb = sb + (cl & 1) * STAGE;
            load_tileH<64, 128>(A, FFN, cl * 64, stb,           tid);
            load_tileH<128, 128>(B, FFN, cl * 64, stb + TILEH64, tid);
            CP_COMMIT();
        }

        uint32_t sA = sb + (uint32_t)((k & 1) * STAGE);
        uint32_t sB = sA + TILEH64;

#pragma unroll
        for (int t = 0; t < 4; ++t) {
            uint32_t kb = (uint32_t)(t * 32);
            uint32_t a[2][4];
            ldsm_x4(a[0][0], a[0][1], a[0][2], a[0][3], sA + aoff + kb);
            ldsm_x4(a[1][0], a[1][1], a[1][2], a[1][3], sA + aoff + 16 * ROWB + kb);

            uint32_t b[8][2];
#pragma unroll
            for (int p = 0; p < 4; ++p)
                ldsm_x4(b[2 * p][0], b[2 * p][1], b[2 * p + 1][0], b[2 * p + 1][1],
                        sB + boff + (uint32_t)(p * 16 * ROWB) + kb);

#pragma unroll
            for (int mi = 0; mi < 2; ++mi)
#pragma unroll
                for (int ni = 0; ni < 8; ++ni)
                    mma16(cc[mi][ni], a[mi][0], a[mi][1], a[mi][2], a[mi][3],
                          b[ni][0], b[ni][1]);
        }
    }

    // epilogue: weighted plain store into per-slot staging buffer
#pragma unroll
    for (int mi = 0; mi < 2; ++mi) {
        int r0 = m0 + wm + mi * 16 + lg;
        int r1 = r0 + 8;
        bool v0 = r0 < cnt, v1 = r1 < cnt;
        float w0 = v0 ? g_tw[e * N_TOK + r0] : 0.0f;
        float w1 = v1 ? g_tw[e * N_TOK + r1] : 0.0f;
        float* o0 = g_Y + ((size_t)e * N_TOK + r0) * HID + n0;
        float* o1 = g_Y + ((size_t)e * N_TOK + r1) * HID + n0;
#pragma unroll
        for (int ni = 0; ni < 8; ++ni) {
            int col = wn + ni * 8 + lc * 2;
            if (v0) {
                float2 p;
                p.x = w0 * cc[mi][ni][0];
                p.y = w0 * cc[mi][ni][1];
                *(float2*)(o0 + col) = p;
            }
            if (v1) {
                float2 p;
                p.x = w1 * cc[mi][ni][2];
                p.y = w1 * cc[mi][ni][3];
                *(float2*)(o1 + col) = p;
            }
        }
    }
}

// ============================ host launcher ============================

extern "C" void kernel_launch(void* const* d_in, const int* in_sizes, int n_in,
                              void* d_out, int out_size) {
    (void)in_sizes; (void)n_in; (void)out_size;
    const float* X  = (const float*)d_in[0];
    const float* Rw = (const float*)d_in[1];
    const float* Gw = (const float*)d_in[2];
    const float* Uw = (const float*)d_in[3];
    const float* Dw = (const float*)d_in[4];
    float* out = (float*)d_out;

    void *pcnt, *pgw, *puw, *pdw;
    cudaGetSymbolAddress(&pcnt, g_cnt);
    cudaGetSymbolAddress(&pgw, g_gwc);
    cudaGetSymbolAddress(&puw, g_uwc);
    cudaGetSymbolAddress(&pdw, g_dwc);

    const int n4 = (int)(GW_ELEMS / 4);
    const int cb = 256;
    const int cg = (n4 + cb - 1) / cb;

    const int SMEM1 = 2 * (3 * TILEH64);          // 55296
    const int SMEM2 = 2 * (TILEH64 + TILEH128);   // 55296
    cudaFuncSetAttribute(gemm1_kernel, cudaFuncAttributeMaxDynamicSharedMemorySize, SMEM1);
    cudaFuncSetAttribute(gemm2_kernel, cudaFuncAttributeMaxDynamicSharedMemorySize, SMEM2);

    // ncu (-s 5 -c 1) profiles the 5th launch (1-based, memsets counted):
    // 1: memset(cnt)  2: routergather  3: cvt3  4: gemm1  5: gemm2  6: combine
    cudaMemsetAsync(pcnt, 0, NEXP * sizeof(int));
    routergather_kernel<<<N_TOK, 128>>>(X, Rw);
    cvt3_kernel<<<dim3(cg, 1, 3), cb>>>(Gw, Uw, Dw,
                                        (__half*)pgw, (__half*)puw, (__half*)pdw, n4);

    gemm1_kernel<<<dim3(FFN / 64, N_TOK / 64, NEXP), 128, SMEM1>>>();
    gemm2_kernel<<<dim3(HID / 128, N_TOK / 64, NEXP), 128, SMEM2>>>();
    combine_kernel<<<N_TOK, 128>>>(out);
}